// round 12
// baseline (speedup 1.0000x reference)
#include <cuda_runtime.h>
#include <cuda_bf16.h>

// Problem constants (fixed by the dataset; arrays sized to them)
#define MAXN 100000
#define MAXE 1200000
#define DIM  64
#define MAXG 128
#define SCAN_B 1024   // elements per scan block

// ---------------- scratch (static device globals; no allocation) -------------
__device__ int   g_indeg[MAXN];
__device__ int   g_fill[MAXN];        // CSR cursor (init = rowptr)
__device__ int   g_rowptr[MAXN + 1];
__device__ float g_dinv[MAXN];
__device__ int   g_col[MAXE];
__device__ __align__(16) __nv_bfloat16 g_tmp[(size_t)MAXN * DIM]; // activations
__device__ __align__(16) __nv_bfloat16 g_h[(size_t)MAXN * DIM];   // gather operand
__device__ __align__(16) __nv_bfloat16 g_Wh[3 * DIM * DIM];       // W hi (bf16)
__device__ __align__(16) __nv_bfloat16 g_Wl[3 * DIM * DIM];       // W lo (bf16)
__device__ float g_pooled[MAXG * DIM];
__device__ int   g_bsum[1024];        // per-block degree sums
__device__ int   g_idx64;             // 1 if indices are int64, 0 if int32

// Flag-dispatched index load (int32[] or int64[]; values < 2^31).
__device__ __forceinline__ int load_idx(const void* p, long long i) {
    if (g_idx64) return (int)((const long long*)p)[i];
    return ((const int*)p)[i];
}

// ---------------- packed helpers ---------------------------------------------
__device__ __forceinline__ void fadd2(unsigned long long& d,
                                      unsigned long long a) {
    asm("add.rn.f32x2 %0,%0,%1;" : "+l"(d) : "l"(a));
}
// accumulate a bf16x2 word into a packed f32x2 accumulator (ALU-pipe unpack)
__device__ __forceinline__ void addbf2(unsigned long long& acc, unsigned int w) {
    unsigned int lo = w << 16;
    unsigned int hi = w & 0xffff0000u;
    unsigned long long p;
    asm("mov.b64 %0,{%1,%2};" : "=l"(p) : "r"(lo), "r"(hi));
    fadd2(acc, p);
}
__device__ __forceinline__ unsigned int bf2(float x, float y) {
    __nv_bfloat162 h = __float22bfloat162_rn(make_float2(x, y));
    return *(unsigned int*)&h;
}
// cp.async 16B with zero-fill when srcsize==0
__device__ __forceinline__ void cpa16(void* smem_dst, const void* gsrc,
                                      int srcsize) {
    unsigned int sa = (unsigned int)__cvta_generic_to_shared(smem_dst);
    asm volatile("cp.async.cg.shared.global [%0], [%1], 16, %2;"
                 :: "r"(sa), "l"(gsrc), "r"(srcsize));
}
union F4U { float4 f4; unsigned long long u[2]; float f[4]; };

// ---------------- detect dtype + zero scratch + W split ----------------------
__global__ void detect_zero_kernel(const int* __restrict__ ei32,
                                   const float* __restrict__ W0,
                                   const float* __restrict__ W1,
                                   const float* __restrict__ W2,
                                   int n, int g) {
    if (blockIdx.x == 0 && threadIdx.x == 0) {
        int all_zero = 1;
        for (int k = 0; k < 32; k++)
            if (ei32[2 * k + 1] != 0) all_zero = 0;
        g_idx64 = all_zero;
    }
    int stride = gridDim.x * blockDim.x;
    int t = blockIdx.x * blockDim.x + threadIdx.x;
    for (int i = t; i < n; i += stride) g_indeg[i] = 0;
    for (int i = t; i < g * DIM; i += stride) g_pooled[i] = 0.0f;
    // split the three weight matrices into bf16 hi + lo (done once per launch)
    for (int i = t; i < 3 * DIM * DIM; i += stride) {
        int w = i >> 12, r = i & 4095;
        float v = (w == 0) ? W0[r] : (w == 1) ? W1[r] : W2[r];
        __nv_bfloat16 h = __float2bfloat16_rn(v);
        __nv_bfloat16 l = __float2bfloat16_rn(v - __bfloat162float(h));
        g_Wh[i] = h;
        g_Wl[i] = l;
    }
}

// ---------------- degree histogram (at destination) --------------------------
__global__ void degree_kernel(const void* __restrict__ ei, int e) {
    int stride = gridDim.x * blockDim.x;
    for (int i = blockIdx.x * blockDim.x + threadIdx.x; i < e; i += stride)
        atomicAdd(&g_indeg[load_idx(ei, (long long)e + i)], 1);
}

// ---------------- scan phase 1: per-block degree sums + dinv -----------------
__global__ void scan1_kernel(int n) {
    __shared__ int wsum[32];
    int b = blockIdx.x, t = threadIdx.x;
    int i = b * SCAN_B + t;
    int lane = t & 31, wi = t >> 5;
    int v = 0;
    if (i < n) {
        v = g_indeg[i];
        g_dinv[i] = rsqrtf((float)v + 1.0f);   // dinv ready before gemm0
    }
    int s = v;
#pragma unroll
    for (int off = 16; off > 0; off >>= 1)
        s += __shfl_down_sync(0xffffffffu, s, off);
    if (lane == 0) wsum[wi] = s;
    __syncthreads();
    if (wi == 0) {
        int z = wsum[lane];
#pragma unroll
        for (int off = 16; off > 0; off >>= 1)
            z += __shfl_down_sync(0xffffffffu, z, off);
        if (lane == 0) g_bsum[b] = z;
    }
}

// ---------------- scan phase 2+3: rowptr + fill cursor -----------------------
__global__ void scan23_kernel(int n) {
    __shared__ int s_boff;
    __shared__ int wtot[32];
    int b = blockIdx.x, t = threadIdx.x;
    int lane = t & 31, wi = t >> 5;
    int i = b * SCAN_B + t;

    if (wi == 0) {
        int sum = 0;
        for (int j = lane; j < b; j += 32) sum += g_bsum[j];
#pragma unroll
        for (int off = 16; off > 0; off >>= 1)
            sum += __shfl_down_sync(0xffffffffu, sum, off);
        if (lane == 0) s_boff = sum;
    }

    int v = (i < n) ? g_indeg[i] : 0;
    int x = v;
#pragma unroll
    for (int off = 1; off < 32; off <<= 1) {
        int y = __shfl_up_sync(0xffffffffu, x, off);
        if (lane >= off) x += y;
    }
    if (lane == 31) wtot[wi] = x;
    __syncthreads();
    if (wi == 0) {
        int y = wtot[lane];
        int z = y;
#pragma unroll
        for (int off = 1; off < 32; off <<= 1) {
            int u = __shfl_up_sync(0xffffffffu, z, off);
            if (lane >= off) z += u;
        }
        wtot[lane] = z - y;
    }
    __syncthreads();

    if (i < n) {
        int excl = x - v + wtot[wi] + s_boff;
        g_rowptr[i] = excl;
        g_fill[i]   = excl;
        if (i == n - 1) g_rowptr[n] = excl + v;
    }
}

// ---------------- CSR fill: col (src) only -----------------------------------
__global__ void fill_kernel(const void* __restrict__ ei, int e) {
    int stride = gridDim.x * blockDim.x;
    for (int i = blockIdx.x * blockDim.x + threadIdx.x; i < e; i += stride) {
        int s = load_idx(ei, i);
        int d = load_idx(ei, (long long)e + i);
        int pos = atomicAdd(&g_fill[d], 1);
        g_col[pos] = s;
    }
}

// ---------------- tensor-core GEMM: g_h = bf16((in @ W) * dinv) --------------
// 128-node x 64-col tile, 8 warps; warp = 16 rows x 64 cols.
// W pre-split into hi+lo bf16 in global (staged via cp.async); A bf16 via
// cp.async (layers 2-3) or LDG+convert (f32 layer 1). Two MMA chains.
__global__ __launch_bounds__(256) void gemm64_kernel(
    const float* __restrict__ xin, int widx, int src16, int n) {
    __shared__ __nv_bfloat16 sA[128][72];    // stride 144B: conflict-free ldsm
    __shared__ __nv_bfloat16 sBh[64][72];    // W hi
    __shared__ __nv_bfloat16 sBl[64][72];    // W lo
    int t = threadIdx.x;
    int block0 = blockIdx.x * 128;

    // stage W hi+lo via cp.async: 2 x 64 rows x 8 chunks of 16B
    for (int idx = t; idx < 1024; idx += 256) {
        int half = idx >> 9;            // 0 = hi, 1 = lo
        int rem = idx & 511;
        int r = rem >> 3, c8 = (rem & 7) << 3;
        const __nv_bfloat16* gp = half ? &g_Wl[widx * 4096 + r * 64 + c8]
                                       : &g_Wh[widx * 4096 + r * 64 + c8];
        void* dp = half ? (void*)&sBl[r][c8] : (void*)&sBh[r][c8];
        cpa16(dp, gp, 16);
    }
    // stage A: 128 rows x 8 chunks of 16B
    if (src16) {
        for (int idx = t; idx < 1024; idx += 256) {
            int r = idx >> 3, c8 = (idx & 7) << 3;
            int node = block0 + r;
            int ok = (node < n);
            const __nv_bfloat16* gp =
                &g_tmp[(size_t)(ok ? node : 0) * 64 + c8];
            cpa16(&sA[r][c8], gp, ok ? 16 : 0);   // zero-fill OOB rows
        }
        asm volatile("cp.async.commit_group;");
        asm volatile("cp.async.wait_group 0;");
    } else {
        asm volatile("cp.async.commit_group;");
        for (int idx = t; idx < 1024; idx += 256) {
            int r = idx >> 3, c8 = (idx & 7) << 3;
            int node = block0 + r;
            uint2 st = make_uint2(0u, 0u);
            if (node < n) {
                float4 x0 = *(const float4*)&xin[(size_t)node * 64 + c8];
                float4 x1 = *(const float4*)&xin[(size_t)node * 64 + c8 + 4];
                st.x = bf2(x0.x, x0.y) | 0u;
                st.y = bf2(x0.z, x0.w);
                *(uint2*)&sA[r][c8] = st;
                st.x = bf2(x1.x, x1.y);
                st.y = bf2(x1.z, x1.w);
                *(uint2*)&sA[r][c8 + 4] = st;
            } else {
                *(uint2*)&sA[r][c8] = st;
                *(uint2*)&sA[r][c8 + 4] = st;
            }
        }
        asm volatile("cp.async.wait_group 0;");
    }
    __syncthreads();

    int w = t >> 5, l = t & 31;
    float acc[8][4] = {};
#pragma unroll
    for (int k0 = 0; k0 < 64; k0 += 16) {
        // A fragment: 16x16, rows w*16..+15
        unsigned int a0, a1, a2, a3;
        {
            int row = (w << 4) + ((l >> 3) & 1) * 8 + (l & 7);
            int col = k0 + (l >> 4) * 8;
            unsigned int ad =
                (unsigned int)__cvta_generic_to_shared(&sA[row][col]);
            asm volatile(
                "ldmatrix.sync.aligned.m8n8.x4.shared.b16 {%0,%1,%2,%3},[%4];"
                : "=r"(a0), "=r"(a1), "=r"(a2), "=r"(a3) : "r"(ad));
        }
        // B fragments (hi and lo): 4 groups of 16 cols (k16 x n16, transposed)
        unsigned int bh[4][4], bl[4][4];
        int krow = k0 + ((l >> 3) & 1) * 8 + (l & 7);
        int bcol = (l >> 4) * 8;
#pragma unroll
        for (int g2 = 0; g2 < 4; g2++) {
            unsigned int adh =
                (unsigned int)__cvta_generic_to_shared(&sBh[krow][g2 * 16 + bcol]);
            asm volatile(
                "ldmatrix.sync.aligned.m8n8.x4.trans.shared.b16 "
                "{%0,%1,%2,%3},[%4];"
                : "=r"(bh[g2][0]), "=r"(bh[g2][1]),
                  "=r"(bh[g2][2]), "=r"(bh[g2][3]) : "r"(adh));
            unsigned int adl =
                (unsigned int)__cvta_generic_to_shared(&sBl[krow][g2 * 16 + bcol]);
            asm volatile(
                "ldmatrix.sync.aligned.m8n8.x4.trans.shared.b16 "
                "{%0,%1,%2,%3},[%4];"
                : "=r"(bl[g2][0]), "=r"(bl[g2][1]),
                  "=r"(bl[g2][2]), "=r"(bl[g2][3]) : "r"(adl));
        }
#pragma unroll
        for (int j = 0; j < 8; j++) {
            unsigned int b0 = bh[j >> 1][(j & 1) * 2];
            unsigned int b1 = bh[j >> 1][(j & 1) * 2 + 1];
            asm volatile(
                "mma.sync.aligned.m16n8k16.row.col.f32.bf16.bf16.f32 "
                "{%0,%1,%2,%3},{%4,%5,%6,%7},{%8,%9},{%0,%1,%2,%3};"
                : "+f"(acc[j][0]), "+f"(acc[j][1]),
                  "+f"(acc[j][2]), "+f"(acc[j][3])
                : "r"(a0), "r"(a1), "r"(a2), "r"(a3), "r"(b0), "r"(b1));
            unsigned int c0 = bl[j >> 1][(j & 1) * 2];
            unsigned int c1 = bl[j >> 1][(j & 1) * 2 + 1];
            asm volatile(
                "mma.sync.aligned.m16n8k16.row.col.f32.bf16.bf16.f32 "
                "{%0,%1,%2,%3},{%4,%5,%6,%7},{%8,%9},{%0,%1,%2,%3};"
                : "+f"(acc[j][0]), "+f"(acc[j][1]),
                  "+f"(acc[j][2]), "+f"(acc[j][3])
                : "r"(a0), "r"(a1), "r"(a2), "r"(a3), "r"(c0), "r"(c1));
        }
    }

    // epilogue: scale by dinv, round to bf16, store
    int r0 = block0 + (w << 4) + (l >> 2);
    int r1 = r0 + 8;
    float d0 = (r0 < n) ? g_dinv[r0] : 0.f;
    float d1 = (r1 < n) ? g_dinv[r1] : 0.f;
#pragma unroll
    for (int j = 0; j < 8; j++) {
        int c = j * 8 + (l & 3) * 2;
        if (r0 < n)
            *(unsigned int*)&g_h[(size_t)r0 * 64 + c] =
                bf2(acc[j][0] * d0, acc[j][1] * d0);
        if (r1 < n)
            *(unsigned int*)&g_h[(size_t)r1 * 64 + c] =
                bf2(acc[j][2] * d1, acc[j][3] * d1);
    }
}

// ---------------- aggregation: warp/node, quarter-warp/edge, bf16 gather -----
// g_tmp[i] = bf16( relu( dinv[i] * ( sum_e g_h[col[e]] + g_h[i] ) + b ) )
__global__ __launch_bounds__(256) void aggregate_kernel(
    const float* __restrict__ b, int n) {
    int warp = (blockIdx.x * blockDim.x + threadIdx.x) >> 5;
    if (warp >= n) return;
    int lane = threadIdx.x & 31;
    int es = lane >> 3;       // edge slot 0..3
    int q = lane & 7;         // 16B feature group (8 bf16 = features 8q..8q+7)
    int s = g_rowptr[warp];
    int e = g_rowptr[warp + 1];
    float di = g_dinv[warp];

    unsigned long long a0 = 0, a1 = 0, a2 = 0, a3 = 0;
    if (es == 0) {            // self term once
        uint4 sv = ((const uint4*)&g_h[(size_t)warp * 64])[q];
        addbf2(a0, sv.x); addbf2(a1, sv.y);
        addbf2(a2, sv.z); addbf2(a3, sv.w);
    }

    // four edges per warp-iteration, depth-2 prefetch (8 gathers in flight)
    int p = s + es;
    int sA = (p < e) ? g_col[p] : -1;
    int sB = (p + 4 < e) ? g_col[p + 4] : -1;
    uint4 vA = make_uint4(0u, 0u, 0u, 0u);
    if (sA >= 0) vA = ((const uint4*)&g_h[(size_t)sA * 64])[q];
    while (p < e) {
        int pn = p + 4;
        int sC = (pn + 4 < e) ? g_col[pn + 4] : -1;
        uint4 vB = make_uint4(0u, 0u, 0u, 0u);
        if (sB >= 0) vB = ((const uint4*)&g_h[(size_t)sB * 64])[q];
        addbf2(a0, vA.x); addbf2(a1, vA.y);
        addbf2(a2, vA.z); addbf2(a3, vA.w);
        vA = vB; sB = sC; p = pn;
    }

    // combine the four quarter-warp accumulators (packed shfl tree)
    fadd2(a0, __shfl_down_sync(0xffffffffu, a0, 16));
    fadd2(a1, __shfl_down_sync(0xffffffffu, a1, 16));
    fadd2(a2, __shfl_down_sync(0xffffffffu, a2, 16));
    fadd2(a3, __shfl_down_sync(0xffffffffu, a3, 16));
    fadd2(a0, __shfl_down_sync(0xffffffffu, a0, 8));
    fadd2(a1, __shfl_down_sync(0xffffffffu, a1, 8));
    fadd2(a2, __shfl_down_sync(0xffffffffu, a2, 8));
    fadd2(a3, __shfl_down_sync(0xffffffffu, a3, 8));

    if (lane < 8) {
        F4U lo4, hi4;
        lo4.u[0] = a0; lo4.u[1] = a1;     // features 8q..8q+3
        hi4.u[0] = a2; hi4.u[1] = a3;     // features 8q+4..8q+7
        float4 bb0 = *(const float4*)&b[q * 8 + 0];
        float4 bb1 = *(const float4*)&b[q * 8 + 4];
        uint4 st;
        st.x = bf2(fmaxf(lo4.f4.x * di + bb0.x, 0.f),
                   fmaxf(lo4.f4.y * di + bb0.y, 0.f));
        st.y = bf2(fmaxf(lo4.f4.z * di + bb0.z, 0.f),
                   fmaxf(lo4.f4.w * di + bb0.w, 0.f));
        st.z = bf2(fmaxf(hi4.f4.x * di + bb1.x, 0.f),
                   fmaxf(hi4.f4.y * di + bb1.y, 0.f));
        st.w = bf2(fmaxf(hi4.f4.z * di + bb1.z, 0.f),
                   fmaxf(hi4.f4.w * di + bb1.w, 0.f));
        *(uint4*)&g_tmp[(size_t)warp * 64 + q * 8] = st;
    }
}

// ---------------- pooling: exploit sorted batch, flush per graph-run ---------
__global__ void pool_kernel(const void* __restrict__ batch, int n) {
    int warp = (blockIdx.x * blockDim.x + threadIdx.x) >> 5;
    int lane = threadIdx.x & 31;
    int base = warp * 64;
    if (base >= n) return;
    int end = min(base + 64, n);
    int cg = load_idx(batch, base);
    float2 acc = make_float2(0.f, 0.f);
    for (int i = base; i < end; i++) {
        int g = load_idx(batch, i);
        if (g != cg) {
            atomicAdd(&g_pooled[cg * 64 + lane * 2 + 0], acc.x);
            atomicAdd(&g_pooled[cg * 64 + lane * 2 + 1], acc.y);
            acc = make_float2(0.f, 0.f);
            cg = g;
        }
        unsigned int wv = *(const unsigned int*)&g_tmp[(size_t)i * 64 + lane * 2];
        float2 v = __bfloat1622float2(*(__nv_bfloat162*)&wv);
        acc.x += v.x;
        acc.y += v.y;
    }
    atomicAdd(&g_pooled[cg * 64 + lane * 2 + 0], acc.x);
    atomicAdd(&g_pooled[cg * 64 + lane * 2 + 1], acc.y);
}

// ---------------- final: counts via binary search + mean + linear head -------
__global__ void final_kernel(const void* __restrict__ batch,
                             const float* __restrict__ lin_w,
                             const float* __restrict__ lin_b,
                             float* __restrict__ out, int n, int g) {
    int i = blockIdx.x * blockDim.x + threadIdx.x;
    if (i >= g) return;
    int lo = 0, hi = n;
    while (lo < hi) {
        int mid = (lo + hi) >> 1;
        if (load_idx(batch, mid) < i) lo = mid + 1; else hi = mid;
    }
    int lb = lo;
    hi = n;
    while (lo < hi) {
        int mid = (lo + hi) >> 1;
        if (load_idx(batch, mid) <= i) lo = mid + 1; else hi = mid;
    }
    float cnt = fmaxf((float)(lo - lb), 1.0f);
    float inv = 1.0f / cnt;
    float a0 = lin_b[0];
    float a1 = lin_b[1];
#pragma unroll
    for (int d = 0; d < 64; d++) {
        float p = g_pooled[i * 64 + d] * inv;
        a0 += p * lin_w[d * 2 + 0];
        a1 += p * lin_w[d * 2 + 1];
    }
    out[i * 2 + 0] = a0;
    out[i * 2 + 1] = a1;
}

// ---------------- launch ------------------------------------------------------
extern "C" void kernel_launch(void* const* d_in, const int* in_sizes, int n_in,
                              void* d_out, int out_size) {
    const float* x     = (const float*)d_in[0];
    const void*  ei    = d_in[1];
    const void*  batch = d_in[2];
    const float* W0    = (const float*)d_in[3];
    const float* b0    = (const float*)d_in[4];
    const float* W1    = (const float*)d_in[5];
    const float* b1    = (const float*)d_in[6];
    const float* W2    = (const float*)d_in[7];
    const float* b2    = (const float*)d_in[8];
    const float* lin_w = (const float*)d_in[9];
    const float* lin_b = (const float*)d_in[10];

    int n = in_sizes[0] / DIM;       // 100000
    int e = in_sizes[1] / 2;         // 1200000
    int nc = in_sizes[10];           // 2
    int g = out_size / nc;           // 128

    int nb = (n + SCAN_B - 1) / SCAN_B;   // 98 scan blocks
    int gemm_blocks = (n + 127) / 128;
    long long agg_threads = (long long)n * 32;
    int agg_blocks = (int)((agg_threads + 255) / 256);

    detect_zero_kernel<<<200, 512>>>((const int*)ei, W0, W1, W2, n, g); // 0
    degree_kernel<<<(e + 511) / 512, 512>>>(ei, e);                // 1
    scan1_kernel<<<nb, SCAN_B>>>(n);                               // 2 (+dinv)
    gemm64_kernel<<<gemm_blocks, 256>>>(x, 0, 0, n);               // 3 <- ncu
    scan23_kernel<<<nb, SCAN_B>>>(n);                              // 4
    fill_kernel<<<(e + 511) / 512, 512>>>(ei, e);                  // 5
    aggregate_kernel<<<agg_blocks, 256>>>(b0, n);                  // 6
    gemm64_kernel<<<gemm_blocks, 256>>>(nullptr, 1, 1, n);         // 7
    aggregate_kernel<<<agg_blocks, 256>>>(b1, n);                  // 8
    gemm64_kernel<<<gemm_blocks, 256>>>(nullptr, 2, 1, n);         // 9
    aggregate_kernel<<<agg_blocks, 256>>>(b2, n);                  // 10
    pool_kernel<<<((n + 63) / 64 * 32 + 255) / 256, 256>>>(batch, n); // 11
    final_kernel<<<1, 128>>>(batch, lin_w, lin_b, (float*)d_out, n, g); // 12
}